// round 8
// baseline (speedup 1.0000x reference)
#include <cuda_runtime.h>

static constexpr int B = 256;
static constexpr int S = 2048;
static constexpr int T = 48;

typedef unsigned long long u64;

// cross-kernel scratch (static __device__: allowed, no dynamic alloc)
__device__ float g_dir[B][2][48];   // [batch][0=alpha_1023 dir, 1=beta_1024 dir]
__device__ float g_c[B][8];         // per-chain log-scales

// ---- packed f32x2 helpers (Blackwell FFMA2: only reachable via PTX) ----
__device__ __forceinline__ u64 pack2(float x, float y) {
    u64 r; asm("mov.b64 %0, {%1, %2};" : "=l"(r) : "f"(x), "f"(y)); return r;
}
__device__ __forceinline__ void unpack2(u64 v, float& x, float& y) {
    asm("mov.b64 {%0, %1}, %2;" : "=f"(x), "=f"(y) : "l"(v));
}
__device__ __forceinline__ u64 ffma2(u64 a, u64 b, u64 c) {
    u64 d; asm("fma.rn.f32x2 %0, %1, %2, %3;" : "=l"(d) : "l"(a), "l"(b), "l"(c)); return d;
}
__device__ __forceinline__ u64 fadd2(u64 a, u64 b) {
    u64 d; asm("add.rn.f32x2 %0, %1, %2;" : "=l"(d) : "l"(a), "l"(b)); return d;
}

// One scaled-exp-domain semiring chain, transposed pair packing (R7 body),
// emission prefetch depth 4 (register diet for 7 blocks/SM).
// BW=0: alpha forward (matvec then *exp(e)); BW=1: beta backward (*exp(e)
// then matvec). Lane l owns states (2l,2l+1); lanes 24..31 padding.
// niter/reset_i/ep RUNTIME -> ONE inlined instance per BW (R5 lesson).
template<int BW>
__device__ __forceinline__ void run_chain(
    const float* __restrict__ ep,    // adjusted emission base (+ j0)
    const u64 (&EA)[24], const u64 (&EB)[24],
    float px, float py, int niter, int reset_i, int lane,
    float2 (*buf)[32],               // per-warp double buffer [2][32]
    float& pxOut, float& pyOut, float& cOut)
{
    int cexp = 0;                    // accumulated power-of-two scale
    float2 ebuf[4];
    int cb = 0;

#define E_OFF(i) ( BW ? (size_t)(S - 1 - (i)) * T : (size_t)((i) + 1) * T )

#pragma unroll
    for (int u = 0; u < 4; ++u)
        ebuf[u] = *(const float2*)(ep + E_OFF(u));   // niter >= 255 always

#define BODY(i, u, RENORM) do {                                            \
    float2 e = ebuf[(u) & 3];                                              \
    int tn = (i) + 4;                                                      \
    if (tn < niter) ebuf[(u) & 3] = *(const float2*)(ep + E_OFF(tn));      \
    float fex = __expf(e.x);                                               \
    float fey = __expf(e.y);                                               \
    float sx = BW ? px * fex : px;                                         \
    float sy = BW ? py * fey : py;                                         \
    buf[cb][lane] = make_float2(sx, sy);                                   \
    __syncwarp();                                                          \
    u64 a0=0ull,a1=0ull,a2=0ull,a3=0ull,a4=0ull,a5=0ull,a6=0ull,a7=0ull;   \
    const float4* bv = (const float4*)buf[cb];                             \
    _Pragma("unroll")                                                      \
    for (int m = 0; m < 12; m += 4) {                                      \
        float4 v0 = bv[m];                                                 \
        u64 b0 = pack2(v0.x, v0.y), b1 = pack2(v0.z, v0.w);                \
        a0 = ffma2(EA[2*m  ], b0, a0);  a4 = ffma2(EB[2*m  ], b0, a4);     \
        a1 = ffma2(EA[2*m+1], b1, a1);  a5 = ffma2(EB[2*m+1], b1, a5);     \
        float4 v1 = bv[m+1];                                               \
        u64 b2 = pack2(v1.x, v1.y), b3 = pack2(v1.z, v1.w);                \
        a2 = ffma2(EA[2*m+2], b2, a2);  a6 = ffma2(EB[2*m+2], b2, a6);     \
        a3 = ffma2(EA[2*m+3], b3, a3);  a7 = ffma2(EB[2*m+3], b3, a7);     \
        float4 v2 = bv[m+2];                                               \
        u64 b4 = pack2(v2.x, v2.y), b5 = pack2(v2.z, v2.w);                \
        a0 = ffma2(EA[2*m+4], b4, a0);  a4 = ffma2(EB[2*m+4], b4, a4);     \
        a1 = ffma2(EA[2*m+5], b5, a1);  a5 = ffma2(EB[2*m+5], b5, a5);     \
        float4 v3 = bv[m+3];                                               \
        u64 b6 = pack2(v3.x, v3.y), b7 = pack2(v3.z, v3.w);                \
        a2 = ffma2(EA[2*m+6], b6, a2);  a6 = ffma2(EB[2*m+6], b6, a6);     \
        a3 = ffma2(EA[2*m+7], b7, a3);  a7 = ffma2(EB[2*m+7], b7, a7);     \
    }                                                                      \
    u64 q0 = fadd2(fadd2(a0, a1), fadd2(a2, a3));                          \
    u64 q1 = fadd2(fadd2(a4, a5), fadd2(a6, a7));                          \
    float x0, y0; unpack2(q0, x0, y0);                                     \
    float x1, y1; unpack2(q1, x1, y1);                                     \
    float n0 = x0 + y0, n1 = x1 + y1;                                      \
    px = BW ? n0 : n0 * fex;                                               \
    py = BW ? n1 : n1 * fey;                                               \
    cb ^= 1;                                                               \
    if (RENORM) {                                                          \
        float ref = __shfl_sync(0xffffffffu, px, 0);                       \
        if ((i) == reset_i) {                                              \
            float inv = __fdividef(1.f, ref);                              \
            px *= inv; py *= inv;                                          \
            cexp = 0;                       /* stitch boundary: discard */ \
        } else {                                                           \
            int ex = (__float_as_int(ref) >> 23) & 255;                    \
            float sc = __int_as_float((254 - ex) << 23); /* 2^(127-ex) */  \
            px *= sc; py *= sc;                                            \
            cexp += ex - 127;                                              \
        }                                                                  \
    }                                                                      \
} while (0)

    int nmain = niter & ~7;
    for (int i = 0; i < nmain; i += 8) {
#pragma unroll
        for (int u = 0; u < 8; ++u) BODY(i + u, u, (u == 7));
    }
#pragma unroll
    for (int u = 0; u < 8; ++u)
        if (nmain + u < niter) BODY(nmain + u, u, false);

    // final exact renorm (lane0-normalize) + exact log of scale
    float c = (float)cexp * 0.69314718055994531f;
    {
        float ref = __shfl_sync(0xffffffffu, px, 0);
        float inv = __fdividef(1.f, ref);
        px *= inv; py *= inv;
        c += __logf(ref);
    }
    pxOut = px; pyOut = py; cOut = c;
#undef BODY
#undef E_OFF
}

// Kernel 1: 1024 blocks x 64 thr. block = (batch b, quarter q).
// warp0 = fw chain q, warp1 = bw chain q.
// PF 8-way split per batch, burn-in 24:
//  fw q=0 exact: t=1..255 (255) ; q>0 burn: trusted t in [q*256 .. q*256+255],
//    burn starts 24 earlier, ep = ep0 + (q*256-25)*T, niter 280, reset i=23.
//    q=3 ends at t=1023 -> dir(alpha_1023).
//  bw q=0 exact: e=2047..1792 (256); q>0 burn: ep = ep0 - (q*256-24)*T,
//    niter 280, reset i=23. q=3 ends at e=1024 -> dir(beta_1024).
__global__ void __launch_bounds__(64, 7)
crf_chains(const float* __restrict__ emis,
           const float* __restrict__ trans,
           const float* __restrict__ startT,
           const float* __restrict__ endT)
{
    __shared__ __align__(16) float2 bufs[2][2][32];  // [warp][double-buf][lane]

    const int blk = blockIdx.x;
    const int b   = blk >> 2;
    const int q   = blk & 3;
    const int tid = threadIdx.x;
    const int w   = tid >> 5;            // 0 = fw, 1 = bw
    const int l   = tid & 31;
    const bool act = l < 24;
    const int j0 = act ? 2*l     : 0;
    const int j1 = act ? 2*l + 1 : 0;

    const size_t base = (size_t)b * S * T;
    const bool fw = (w == 0);

    // per-lane exp(transition) pair constants (96 regs), transposed packing
    u64 EA[24], EB[24];
    if (fw) {
#pragma unroll
        for (int k = 0; k < 24; ++k) {
            float a0 = __expf(trans[(2*k)*T   + j0]);
            float a1 = __expf(trans[(2*k+1)*T + j0]);
            float b0 = __expf(trans[(2*k)*T   + j1]);
            float b1 = __expf(trans[(2*k+1)*T + j1]);
            EA[k] = act ? pack2(a0, a1) : 0ull;
            EB[k] = act ? pack2(b0, b1) : 0ull;
        }
    } else {
#pragma unroll
        for (int k = 0; k < 24; ++k) {
            float a0 = __expf(trans[j0*T + 2*k]);
            float a1 = __expf(trans[j0*T + 2*k+1]);
            float b0 = __expf(trans[j1*T + 2*k]);
            float b1 = __expf(trans[j1*T + 2*k+1]);
            EA[k] = act ? pack2(a0, a1) : 0ull;
            EB[k] = act ? pack2(b0, b1) : 0ull;
        }
    }

    const float* ep0 = emis + base + j0;

    const int niter = (q == 0) ? (fw ? 255 : 256) : 280;
    const int reset = (q == 0) ? -1 : 23;

    const float* ep;
    float p0x, p0y;
    if (fw) {
        ep = (q == 0) ? ep0 : ep0 + (size_t)(q*256 - 25) * T;
        if (q == 0) {
            float2 e0 = *(const float2*)ep0;                  // t = 0
            p0x = act ? __expf(startT[j0] + e0.x) : 0.f;
            p0y = act ? __expf(startT[j1] + e0.y) : 0.f;
        } else { p0x = act ? 1.f : 0.f; p0y = p0x; }
    } else {
        ep = (q == 0) ? ep0 : ep0 - (size_t)(q*256 - 24) * T;
        if (q == 0) {
            p0x = act ? __expf(endT[j0]) : 0.f;
            p0y = act ? __expf(endT[j1]) : 0.f;
        } else { p0x = act ? 1.f : 0.f; p0y = p0x; }
    }

    float pfx, pfy, c;
    if (fw) run_chain<0>(ep, EA, EB, p0x, p0y, niter, reset, l, bufs[0], pfx, pfy, c);
    else    run_chain<1>(ep, EA, EB, p0x, p0y, niter, reset, l, bufs[1], pfx, pfy, c);

    if (q == 3 && act) {                 // boundary direction vectors
        g_dir[b][w][2*l]   = pfx;
        g_dir[b][w][2*l+1] = pfy;
    }
    if (l == 0) g_c[b][w*4 + q] = c;
}

// Kernel 2: combine + numerator. grid B x 64 thr.
__global__ void __launch_bounds__(64)
crf_combine(const float* __restrict__ emis,
            const int*   __restrict__ tagsw,   // int32 view; int64 auto-detected
            const int*   __restrict__ mask,
            const float* __restrict__ trans,
            const float* __restrict__ startT,
            const float* __restrict__ endT,
            float* __restrict__ out)
{
    __shared__ float shRed[64];
    const int b   = blockIdx.x;
    const int tid = threadIdx.x;
    const size_t base = (size_t)b * S * T;

    shRed[tid] = (tid < 48) ? g_dir[b][0][tid] * g_dir[b][1][tid] : 0.f;
    __syncthreads();

    float Z = 0.f;
    if (tid == 0) {
        float dot = 0.f;
#pragma unroll
        for (int k = 0; k < 48; ++k) dot += shRed[k];
        float cs = 0.f;
#pragma unroll
        for (int k = 0; k < 8; ++k) cs += g_c[b][k];
        Z = __logf(dot) + cs;            // log-partition (denominator)
    }

    // ---- tags dtype detection: int64 iff sampled odd 32-bit words all zero ----
    int oddw = tagsw[2*tid + 1];
    int any  = __syncthreads_or(oddw != 0);          // also orders shRed reuse
    const bool is64 = (any == 0);

    // ---- numerator: gold-path score ----
    const size_t tbase = (size_t)b * S;
    float num = 0.f;
#pragma unroll 4
    for (int k = 0; k < 32; ++k) {
        int s = tid + 64*k;
        int cur = is64 ? tagsw[(tbase + s) * 2] : tagsw[tbase + s];
        if (s == 0) {
            num += startT[cur] + emis[base + cur];
        } else {
            int prev = is64 ? tagsw[(tbase + s - 1) * 2] : tagsw[tbase + s - 1];
            float m = (float)mask[tbase + s];
            num += (trans[prev*T + cur] + emis[base + (size_t)s*T + cur]) * m;
        }
        if (s == S - 1) num += endT[cur];
    }
    shRed[tid] = num;
    __syncthreads();
    if (tid == 0) {
        float tot = 0.f;
#pragma unroll
        for (int k = 0; k < 64; ++k) tot += shRed[k];
        out[b] = Z - tot;                            // NLL
    }
}

extern "C" void kernel_launch(void* const* d_in, const int* in_sizes, int n_in,
                              void* d_out, int out_size) {
    (void)in_sizes; (void)n_in; (void)out_size;
    const float* emis   = (const float*)d_in[0];
    const int*   tagsw  = (const int*)  d_in[1];
    const int*   mask   = (const int*)  d_in[2];
    const float* trans  = (const float*)d_in[3];
    const float* startT = (const float*)d_in[4];
    const float* endT   = (const float*)d_in[5];
    crf_chains <<<B * 4, 64>>>(emis, trans, startT, endT);
    crf_combine<<<B,     64>>>(emis, tagsw, mask, trans, startT, endT, (float*)d_out);
}

// round 9
// speedup vs baseline: 1.0814x; 1.0814x over previous
#include <cuda_runtime.h>

static constexpr int B = 256;
static constexpr int S = 2048;
static constexpr int T = 48;

typedef unsigned long long u64;

// cross-kernel scratch (static __device__: allowed, no dynamic alloc)
__device__ float g_dir[B][2][48];   // [batch][0=alpha_1023 dir, 1=beta_1024 dir]
__device__ float g_c[B][8];         // per-chain log-scales
__device__ float g_num[B][4];       // per-quarter numerator partials

// ---- packed f32x2 helpers (Blackwell FFMA2: only reachable via PTX) ----
__device__ __forceinline__ u64 pack2(float x, float y) {
    u64 r; asm("mov.b64 %0, {%1, %2};" : "=l"(r) : "f"(x), "f"(y)); return r;
}
__device__ __forceinline__ void unpack2(u64 v, float& x, float& y) {
    asm("mov.b64 {%0, %1}, %2;" : "=f"(x), "=f"(y) : "l"(v));
}
__device__ __forceinline__ u64 ffma2(u64 a, u64 b, u64 c) {
    u64 d; asm("fma.rn.f32x2 %0, %1, %2, %3;" : "=l"(d) : "l"(a), "l"(b), "l"(c)); return d;
}
__device__ __forceinline__ u64 fadd2(u64 a, u64 b) {
    u64 d; asm("add.rn.f32x2 %0, %1, %2;" : "=l"(d) : "l"(a), "l"(b)); return d;
}

// One scaled-exp-domain semiring chain, transposed pair packing, prefetch 4.
// BW=0: alpha forward (matvec then *exp(e)); BW=1: beta backward (*exp(e)
// then matvec). Lane l owns states (2l,2l+1); lanes 24..31 padding.
// niter/reset_i/ep RUNTIME -> ONE inlined instance per BW (R5 lesson).
template<int BW>
__device__ __forceinline__ void run_chain(
    const float* __restrict__ ep,    // adjusted emission base (+ j0)
    const u64 (&EA)[24], const u64 (&EB)[24],
    float px, float py, int niter, int reset_i, int lane,
    float2 (*buf)[32],               // per-warp double buffer [2][32]
    float& pxOut, float& pyOut, float& cOut)
{
    int cexp = 0;                    // accumulated power-of-two scale
    float2 ebuf[4];
    int cb = 0;

#define E_OFF(i) ( BW ? (size_t)(S - 1 - (i)) * T : (size_t)((i) + 1) * T )

#pragma unroll
    for (int u = 0; u < 4; ++u)
        ebuf[u] = *(const float2*)(ep + E_OFF(u));   // niter >= 255 always

#define BODY(i, u, RENORM) do {                                            \
    float2 e = ebuf[(u) & 3];                                              \
    int tn = (i) + 4;                                                      \
    if (tn < niter) ebuf[(u) & 3] = *(const float2*)(ep + E_OFF(tn));      \
    float fex = __expf(e.x);                                               \
    float fey = __expf(e.y);                                               \
    float sx = BW ? px * fex : px;                                         \
    float sy = BW ? py * fey : py;                                         \
    buf[cb][lane] = make_float2(sx, sy);                                   \
    __syncwarp();                                                          \
    u64 a0=0ull,a1=0ull,a2=0ull,a3=0ull,a4=0ull,a5=0ull,a6=0ull,a7=0ull;   \
    const float4* bv = (const float4*)buf[cb];                             \
    _Pragma("unroll")                                                      \
    for (int m = 0; m < 12; m += 4) {                                      \
        float4 v0 = bv[m];                                                 \
        u64 b0 = pack2(v0.x, v0.y), b1 = pack2(v0.z, v0.w);                \
        a0 = ffma2(EA[2*m  ], b0, a0);  a4 = ffma2(EB[2*m  ], b0, a4);     \
        a1 = ffma2(EA[2*m+1], b1, a1);  a5 = ffma2(EB[2*m+1], b1, a5);     \
        float4 v1 = bv[m+1];                                               \
        u64 b2 = pack2(v1.x, v1.y), b3 = pack2(v1.z, v1.w);                \
        a2 = ffma2(EA[2*m+2], b2, a2);  a6 = ffma2(EB[2*m+2], b2, a6);     \
        a3 = ffma2(EA[2*m+3], b3, a3);  a7 = ffma2(EB[2*m+3], b3, a7);     \
        float4 v2 = bv[m+2];                                               \
        u64 b4 = pack2(v2.x, v2.y), b5 = pack2(v2.z, v2.w);                \
        a0 = ffma2(EA[2*m+4], b4, a0);  a4 = ffma2(EB[2*m+4], b4, a4);     \
        a1 = ffma2(EA[2*m+5], b5, a1);  a5 = ffma2(EB[2*m+5], b5, a5);     \
        float4 v3 = bv[m+3];                                               \
        u64 b6 = pack2(v3.x, v3.y), b7 = pack2(v3.z, v3.w);                \
        a2 = ffma2(EA[2*m+6], b6, a2);  a6 = ffma2(EB[2*m+6], b6, a6);     \
        a3 = ffma2(EA[2*m+7], b7, a3);  a7 = ffma2(EB[2*m+7], b7, a7);     \
    }                                                                      \
    u64 q0 = fadd2(fadd2(a0, a1), fadd2(a2, a3));                          \
    u64 q1 = fadd2(fadd2(a4, a5), fadd2(a6, a7));                          \
    float x0, y0; unpack2(q0, x0, y0);                                     \
    float x1, y1; unpack2(q1, x1, y1);                                     \
    float n0 = x0 + y0, n1 = x1 + y1;                                      \
    px = BW ? n0 : n0 * fex;                                               \
    py = BW ? n1 : n1 * fey;                                               \
    cb ^= 1;                                                               \
    if (RENORM) {                                                          \
        float ref = __shfl_sync(0xffffffffu, px, 0);                       \
        if ((i) == reset_i) {                                              \
            float inv = __fdividef(1.f, ref);                              \
            px *= inv; py *= inv;                                          \
            cexp = 0;                       /* stitch boundary: discard */ \
        } else {                                                           \
            int ex = (__float_as_int(ref) >> 23) & 255;                    \
            float sc = __int_as_float((254 - ex) << 23); /* 2^(127-ex) */  \
            px *= sc; py *= sc;                                            \
            cexp += ex - 127;                                              \
        }                                                                  \
    }                                                                      \
} while (0)

    int nmain = niter & ~7;
    for (int i = 0; i < nmain; i += 8) {
#pragma unroll
        for (int u = 0; u < 8; ++u) BODY(i + u, u, (u == 7));
    }
#pragma unroll
    for (int u = 0; u < 8; ++u)
        if (nmain + u < niter) BODY(nmain + u, u, false);

    // final exact renorm (lane0-normalize) + exact log of scale
    float c = (float)cexp * 0.69314718055994531f;
    {
        float ref = __shfl_sync(0xffffffffu, px, 0);
        float inv = __fdividef(1.f, ref);
        px *= inv; py *= inv;
        c += __logf(ref);
    }
    pxOut = px; pyOut = py; cOut = c;
#undef BODY
#undef E_OFF
}

// Kernel 1: 1024 blocks x 64 thr, FORCED 7 blocks/SM (<=146 regs) so the
// 8-way PF split runs in ONE wave of 280-step chains (R8's 2-wave failure).
// block = (batch b, quarter q); warp0 = fw chain q, warp1 = bw chain q.
// Indexing identical to R8 (validated, rel_err 2.76e-7).
// Epilogue: per-block partial numerator over s in [q*512, (q+1)*512).
__global__ void __launch_bounds__(64, 7)
crf_chains(const float* __restrict__ emis,
           const int*   __restrict__ tagsw,
           const int*   __restrict__ mask,
           const float* __restrict__ trans,
           const float* __restrict__ startT,
           const float* __restrict__ endT)
{
    __shared__ __align__(16) float2 bufs[2][2][32];  // [warp][double-buf][lane]
    __shared__ float shRed[64];

    const int blk = blockIdx.x;
    const int b   = blk >> 2;
    const int q   = blk & 3;
    const int tid = threadIdx.x;
    const int w   = tid >> 5;            // 0 = fw, 1 = bw
    const int l   = tid & 31;
    const bool act = l < 24;
    const int j0 = act ? 2*l     : 0;
    const int j1 = act ? 2*l + 1 : 0;

    const size_t base = (size_t)b * S * T;
    const bool fw = (w == 0);

    // per-lane exp(transition) pair constants (96 regs), transposed packing
    u64 EA[24], EB[24];
    if (fw) {
#pragma unroll
        for (int k = 0; k < 24; ++k) {
            float a0 = __expf(trans[(2*k)*T   + j0]);
            float a1 = __expf(trans[(2*k+1)*T + j0]);
            float b0 = __expf(trans[(2*k)*T   + j1]);
            float b1 = __expf(trans[(2*k+1)*T + j1]);
            EA[k] = act ? pack2(a0, a1) : 0ull;
            EB[k] = act ? pack2(b0, b1) : 0ull;
        }
    } else {
#pragma unroll
        for (int k = 0; k < 24; ++k) {
            float a0 = __expf(trans[j0*T + 2*k]);
            float a1 = __expf(trans[j0*T + 2*k+1]);
            float b0 = __expf(trans[j1*T + 2*k]);
            float b1 = __expf(trans[j1*T + 2*k+1]);
            EA[k] = act ? pack2(a0, a1) : 0ull;
            EB[k] = act ? pack2(b0, b1) : 0ull;
        }
    }

    const float* ep0 = emis + base + j0;

    const int niter = (q == 0) ? (fw ? 255 : 256) : 280;
    const int reset = (q == 0) ? -1 : 23;

    const float* ep;
    float p0x, p0y;
    if (fw) {
        ep = (q == 0) ? ep0 : ep0 + (size_t)(q*256 - 25) * T;
        if (q == 0) {
            float2 e0 = *(const float2*)ep0;                  // t = 0
            p0x = act ? __expf(startT[j0] + e0.x) : 0.f;
            p0y = act ? __expf(startT[j1] + e0.y) : 0.f;
        } else { p0x = act ? 1.f : 0.f; p0y = p0x; }
    } else {
        ep = (q == 0) ? ep0 : ep0 - (size_t)(q*256 - 24) * T;
        if (q == 0) {
            p0x = act ? __expf(endT[j0]) : 0.f;
            p0y = act ? __expf(endT[j1]) : 0.f;
        } else { p0x = act ? 1.f : 0.f; p0y = p0x; }
    }

    float pfx, pfy, c;
    if (fw) run_chain<0>(ep, EA, EB, p0x, p0y, niter, reset, l, bufs[0], pfx, pfy, c);
    else    run_chain<1>(ep, EA, EB, p0x, p0y, niter, reset, l, bufs[1], pfx, pfy, c);

    if (q == 3 && act) {                 // boundary direction vectors
        g_dir[b][w][2*l]   = pfx;
        g_dir[b][w][2*l+1] = pfy;
    }
    if (l == 0) g_c[b][w*4 + q] = c;

    // ---- tags dtype detection: int64 iff sampled odd 32-bit words all zero ----
    int oddw = tagsw[2*tid + 1];
    int any  = __syncthreads_or(oddw != 0);
    const bool is64 = (any == 0);

    // ---- partial numerator over this block's quarter: s in [q*512, q*512+512) ----
    const size_t tbase = (size_t)b * S;
    const int s0 = q * 512;
    float num = 0.f;
#pragma unroll
    for (int k = 0; k < 8; ++k) {
        int s = s0 + tid + 64*k;
        int cur = is64 ? tagsw[(tbase + s) * 2] : tagsw[tbase + s];
        if (s == 0) {
            num += startT[cur] + emis[base + cur];
        } else {
            int prev = is64 ? tagsw[(tbase + s - 1) * 2] : tagsw[tbase + s - 1];
            float m = (float)mask[tbase + s];
            num += (trans[prev*T + cur] + emis[base + (size_t)s*T + cur]) * m;
        }
        if (s == S - 1) num += endT[cur];
    }
    shRed[tid] = num;
    __syncthreads();
    if (tid == 0) {
        float tot = 0.f;
#pragma unroll
        for (int k = 0; k < 64; ++k) tot += shRed[k];
        g_num[b][q] = tot;
    }
}

// Kernel 2: tiny combine. grid B x 64 thr.
__global__ void __launch_bounds__(64)
crf_combine(float* __restrict__ out)
{
    __shared__ float shRed[64];
    const int b   = blockIdx.x;
    const int tid = threadIdx.x;

    shRed[tid] = (tid < 48) ? g_dir[b][0][tid] * g_dir[b][1][tid] : 0.f;
    __syncthreads();

    if (tid == 0) {
        float dot = 0.f;
#pragma unroll
        for (int k = 0; k < 48; ++k) dot += shRed[k];
        float cs = 0.f;
#pragma unroll
        for (int k = 0; k < 8; ++k) cs += g_c[b][k];
        float nm = g_num[b][0] + g_num[b][1] + g_num[b][2] + g_num[b][3];
        out[b] = __logf(dot) + cs - nm;              // NLL
    }
}

extern "C" void kernel_launch(void* const* d_in, const int* in_sizes, int n_in,
                              void* d_out, int out_size) {
    (void)in_sizes; (void)n_in; (void)out_size;
    const float* emis   = (const float*)d_in[0];
    const int*   tagsw  = (const int*)  d_in[1];
    const int*   mask   = (const int*)  d_in[2];
    const float* trans  = (const float*)d_in[3];
    const float* startT = (const float*)d_in[4];
    const float* endT   = (const float*)d_in[5];
    crf_chains <<<B * 4, 64>>>(emis, tagsw, mask, trans, startT, endT);
    crf_combine<<<B, 64>>>((float*)d_out);
}